// round 5
// baseline (speedup 1.0000x reference)
#include <cuda_runtime.h>

#define EPS 1e-7f
#define LN2 0.69314718055994530942f

#define NB 16
#define NH 56
#define NW 56
#define NC 128
#define HW   (NH*NW)                 // 3136
#define PLANE (NH*NW*NC)             // 401408
#define NTOT (NB*NH*NW*NC)           // 6422528
#define SATW 57
#define SATROW (SATW*NC)             // 7296
#define SATPLANE (SATW*SATW*NC)      // 415872

// -------- scratch (static device globals; no runtime allocation) --------
__device__ float    g_sat[(size_t)NB*SATPLANE];   // padded SAT of (xs-0.5)
__device__ float    g_P[NTOT];                    // sim * sigmoid(alpha_norm)
__device__ float    g_Q[NTOT];                    // (1-sim) * xs
__device__ unsigned g_umin[NB], g_umax[NB];
__device__ float    g_part[NB*NH*NC];             // per-(b,h,c) alpha partial sums
__device__ float    g_excite[NB*NC];
__device__ float    g_u[5];
__device__ float    g_normu;

// order-preserving float <-> uint mapping for atomic min/max
__device__ __forceinline__ unsigned fmap(float f){
    unsigned u = __float_as_uint(f);
    return (u >> 31) ? ~u : (u | 0x80000000u);
}
__device__ __forceinline__ float funmap(unsigned u){
    return __uint_as_float((u >> 31) ? (u & 0x7fffffffu) : ~u);
}

// -------- K0: init scratch + precompute u vector from kappa --------
__global__ void k0_init(const float* __restrict__ kappa){
    int t = threadIdx.x;
    if (t < NB){ g_umin[t] = 0xFFFFFFFFu; g_umax[t] = 0u; }
    if (t == 0){
        float v[5], mean = 0.f;
        #pragma unroll
        for (int s = 0; s < 5; s++){
            float kk = 1.f/(1.f + expf(-kappa[s]));          // sigmoid(kappa)
            float lk = 1.f/(1.f + expf(-logf(kk + EPS)));    // sigmoid(log(k_+eps))
            v[s] = lk + (float)(s+1)*LN2;                    // log_k + log_r
            mean += v[s];
        }
        mean *= 0.2f;
        float n2 = 0.f;
        #pragma unroll
        for (int s = 0; s < 5; s++){ g_u[s] = v[s] - mean; n2 += g_u[s]*g_u[s]; }
        g_normu = sqrtf(n2);
    }
}

// -------- K1: per-sample min/max --------
__global__ void k1_minmax(const float* __restrict__ x){
    int b = blockIdx.y;
    const float* xb = x + (size_t)b*PLANE;
    float mn = 3.4e38f, mx = -3.4e38f;
    for (int i = blockIdx.x*blockDim.x + threadIdx.x; i < PLANE; i += gridDim.x*blockDim.x){
        float v = xb[i];
        mn = fminf(mn, v); mx = fmaxf(mx, v);
    }
    #pragma unroll
    for (int o = 16; o; o >>= 1){
        mn = fminf(mn, __shfl_down_sync(~0u, mn, o));
        mx = fmaxf(mx, __shfl_down_sync(~0u, mx, o));
    }
    __shared__ float smn[8], smx[8];
    int w = threadIdx.x >> 5, l = threadIdx.x & 31;
    if (l == 0){ smn[w] = mn; smx[w] = mx; }
    __syncthreads();
    if (threadIdx.x < 8){
        mn = smn[threadIdx.x]; mx = smx[threadIdx.x];
        #pragma unroll
        for (int o = 4; o; o >>= 1){
            mn = fminf(mn, __shfl_down_sync(0xff, mn, o));
            mx = fmaxf(mx, __shfl_down_sync(0xff, mx, o));
        }
        if (threadIdx.x == 0){
            atomicMin(&g_umin[b], fmap(mn));
            atomicMax(&g_umax[b], fmap(mx));
        }
    }
}

// -------- K2a: normalize + row prefix (writes padded SAT rows; row 0 = zeros) --------
__global__ void k2a_rowpref(const float* __restrict__ x){
    int b = blockIdx.y, hh = blockIdx.x, c = threadIdx.x;
    float* satb = g_sat + (size_t)b*SATPLANE;
    if (hh == 0){
        for (int w = 0; w < SATW; w++) satb[w*NC + c] = 0.f;
        return;
    }
    int h = hh - 1;
    float xmin = funmap(g_umin[b]);
    float xmax = funmap(g_umax[b]);
    float inv  = 1.f/(xmax - xmin + EPS);
    const float* xr = x + ((size_t)(b*NH + h))*NW*NC + c;
    float* sr = satb + (size_t)hh*SATROW + c;
    sr[0] = 0.f;
    float acc = 0.f;
    for (int w = 0; w < NW; w++){
        float xs = (xr[w*NC] - xmin)*inv;
        acc += xs - 0.5f;                // store centered values for precision
        sr[(w+1)*NC] = acc;
    }
}

// -------- K2b: column prefix in place --------
__global__ void k2b_colpref(){
    int b = blockIdx.y;
    int idx = blockIdx.x*blockDim.x + threadIdx.x;   // 0..7167
    int cw = idx >> 7, c = idx & 127;
    float* p = g_sat + (size_t)b*SATPLANE + (size_t)(cw+1)*NC + c;
    float acc = 0.f;
    for (int hh = 1; hh <= NH; hh++){
        float v = p[(size_t)hh*SATROW];
        acc += v;
        p[(size_t)hh*SATROW] = acc;
    }
}

// -------- K3: main per-pixel kernel --------
__global__ void __launch_bounds__(256) k3_main(
    const float* __restrict__ x,
    const float* __restrict__ gamma, const float* __restrict__ beta,
    const float* __restrict__ bnm,   const float* __restrict__ bnv)
{
    int b = blockIdx.y, h = blockIdx.x;
    int c = threadIdx.x & 127, half = threadIdx.x >> 7;
    const float* __restrict__ satb = g_sat + (size_t)b*SATPLANE;

    float xmin = funmap(g_umin[b]);
    float inv  = 1.f/(funmap(g_umax[b]) - xmin + EPS);
    float u0 = g_u[0], u1 = g_u[1], u2 = g_u[2], u3 = g_u[3], u4 = g_u[4];
    float normu = g_normu;
    float ga = gamma[c], be = beta[c], bm = bnm[c];
    float rstd = rsqrtf(bnv[c] + 1e-3f);

    const float* __restrict__ rowA[5];
    const float* __restrict__ rowB[5];
    float rhf[5]; int lo[5], hi[5];
    #pragma unroll
    for (int s = 0; s < 5; s++){
        int k = 2 << s;                  // 2,4,8,16,32
        lo[s] = k/2 - 1; hi[s] = k/2;    // TF SAME padding for even k
        int r0 = max(0, h - lo[s]), r1 = min(NH-1, h + hi[s]);
        rowA[s] = satb + (size_t)r0    *SATROW + c;   // = S(r0-1, .)
        rowB[s] = satb + (size_t)(r1+1)*SATROW + c;   // = S(r1,   .)
        rhf[s]  = (float)(r1 - r0 + 1);
    }

    float asum = 0.f;
    int wbeg = half*28;
    #pragma unroll 4
    for (int w = wbeg; w < wbeg + 28; w++){
        float lm[5], slm = 0.f;
        #pragma unroll
        for (int s = 0; s < 5; s++){
            int cA = max(0, w - lo[s]);            // padded-SAT col of (c0-1)+1
            int cB = min(NW-1, w + hi[s]) + 1;     // padded-SAT col of c1+1
            float Ssum = rowB[s][cB*NC] - rowA[s][cB*NC]
                       - rowB[s][cA*NC] + rowA[s][cA*NC];
            float m = Ssum + 0.5f*rhf[s]*(float)(cB - cA);   // undo centering
            lm[s] = __logf(m + EPS);
            slm += lm[s];
        }
        float alpha = (-2.f*lm[0] - lm[1] + lm[3] + 2.f*lm[4]) * (1.f/(10.f*LN2));
        float mean = 0.2f*slm;
        float a0 = lm[0]-mean, a1 = lm[1]-mean, a2 = lm[2]-mean, a3 = lm[3]-mean, a4 = lm[4]-mean;
        float dot = a0*u0 + a1*u1 + a2*u2 + a3*u3 + a4*u4;
        float na  = sqrtf(a0*a0 + a1*a1 + a2*a2 + a3*a3 + a4*a4);
        float cosv = alpha*dot / (na*fabsf(alpha)*normu + EPS);
        float sim = 0.5f*(cosv + 1.f);
        float an = ga*(alpha - bm)*rstd + be;
        float sa = 1.f/(1.f + __expf(-an));
        size_t o = ((size_t)(b*NH + h)*NW + w)*NC + c;
        float xs = (x[o] - xmin)*inv;
        g_P[o] = sim*sa;
        g_Q[o] = (1.f - sim)*xs;
        asum += alpha;
    }
    __shared__ float sh[256];
    sh[threadIdx.x] = asum;
    __syncthreads();
    if (half == 0)
        g_part[((size_t)b*NH + h)*NC + c] = sh[c] + sh[c + 128];
}

// -------- K4: squeeze-excite MLP --------
__global__ void k4_se(const float* __restrict__ W1, const float* __restrict__ b1,
                      const float* __restrict__ W2, const float* __restrict__ b2){
    int b = blockIdx.x, t = threadIdx.x;
    __shared__ float sq[NC], hid[16];
    float s = 0.f;
    const float* pb = g_part + (size_t)b*NH*NC + t;
    for (int h = 0; h < NH; h++) s += pb[h*NC];
    sq[t] = s * (1.f/(float)HW);
    __syncthreads();
    if (t < 16){
        float a = b1[t];
        for (int cc = 0; cc < NC; cc++) a += sq[cc]*W1[cc*16 + t];
        hid[t] = fmaxf(a, 0.f);
    }
    __syncthreads();
    float e = b2[t];
    #pragma unroll
    for (int j = 0; j < 16; j++) e += hid[j]*W2[j*NC + t];
    g_excite[b*NC + t] = 1.f/(1.f + expf(-e));
}

// -------- K5: final combine --------
__global__ void k5_out(float* __restrict__ out){
    for (int i4 = blockIdx.x*blockDim.x + threadIdx.x; i4 < NTOT/4;
         i4 += gridDim.x*blockDim.x){
        size_t i = (size_t)i4*4;
        int b  = (int)(i / PLANE);
        int c0 = (int)(i & 127);
        float4 P = *(const float4*)(g_P + i);
        float4 Q = *(const float4*)(g_Q + i);
        float4 E = *(const float4*)(g_excite + b*NC + c0);
        float4 o;
        o.x = P.x + Q.x*E.x;
        o.y = P.y + Q.y*E.y;
        o.z = P.z + Q.z*E.z;
        o.w = P.w + Q.w*E.w;
        *(float4*)(out + i) = o;
    }
}

extern "C" void kernel_launch(void* const* d_in, const int* in_sizes, int n_in,
                              void* d_out, int out_size){
    const float* x     = (const float*)d_in[0];
    const float* kappa = (const float*)d_in[1];
    const float* W1    = (const float*)d_in[2];
    const float* b1    = (const float*)d_in[3];
    const float* W2    = (const float*)d_in[4];
    const float* b2    = (const float*)d_in[5];
    const float* gamma = (const float*)d_in[6];
    const float* beta  = (const float*)d_in[7];
    const float* bnm   = (const float*)d_in[8];
    const float* bnv   = (const float*)d_in[9];
    float* out = (float*)d_out;

    k0_init   <<<1, 256>>>(kappa);
    k1_minmax <<<dim3(32, NB), 256>>>(x);
    k2a_rowpref<<<dim3(SATW, NB), 128>>>(x);
    k2b_colpref<<<dim3(28, NB), 256>>>();
    k3_main   <<<dim3(NH, NB), 256>>>(x, gamma, beta, bnm, bnv);
    k4_se     <<<NB, 128>>>(W1, b1, W2, b2);
    k5_out    <<<(NTOT/4 + 255)/256, 256>>>(out);
}

// round 8
// speedup vs baseline: 1.1863x; 1.1863x over previous
#include <cuda_runtime.h>

#define EPS 1e-7f
#define LN2 0.69314718055994530942f

#define NB 16
#define NH 56
#define NW 56
#define NC 128
#define HW   (NH*NW)                 // 3136
#define PLANE (NH*NW*NC)             // 401408
#define NTOT (NB*NH*NW*NC)           // 6422528
#define SATW 57
#define SATROW (SATW*NC)             // 7296
#define SATPLANE (SATW*SATW*NC)      // 415872

// -------- scratch (static device globals; no runtime allocation) --------
__device__ float    g_sat[(size_t)NB*SATPLANE];   // padded SAT of (xs-0.5)
__device__ unsigned g_PQ[NTOT];                   // packed unorm16: P | Q<<16
__device__ unsigned g_umin[NB], g_umax[NB];
__device__ float    g_part[NB*NH*NC];             // per-(b,h,c) alpha partial sums
__device__ float    g_excite[NB*NC];
__device__ float    g_u[5];
__device__ float    g_normu;

// order-preserving float <-> uint mapping for atomic min/max
__device__ __forceinline__ unsigned fmap(float f){
    unsigned u = __float_as_uint(f);
    return (u >> 31) ? ~u : (u | 0x80000000u);
}
__device__ __forceinline__ float funmap(unsigned u){
    return __uint_as_float((u >> 31) ? (u & 0x7fffffffu) : ~u);
}

// -------- K0: init scratch + precompute u vector from kappa --------
__global__ void k0_init(const float* __restrict__ kappa){
    int t = threadIdx.x;
    if (t < NB){ g_umin[t] = 0xFFFFFFFFu; g_umax[t] = 0u; }
    if (t == 0){
        float v[5], mean = 0.f;
        #pragma unroll
        for (int s = 0; s < 5; s++){
            float kk = 1.f/(1.f + expf(-kappa[s]));          // sigmoid(kappa)
            float lk = 1.f/(1.f + expf(-logf(kk + EPS)));    // sigmoid(log(k_+eps))
            v[s] = lk + (float)(s+1)*LN2;                    // log_k + log_r
            mean += v[s];
        }
        mean *= 0.2f;
        float n2 = 0.f;
        #pragma unroll
        for (int s = 0; s < 5; s++){ g_u[s] = v[s] - mean; n2 += g_u[s]*g_u[s]; }
        g_normu = sqrtf(n2);
    }
}

// -------- K1: per-sample min/max (float4 streaming) --------
__global__ void k1_minmax(const float* __restrict__ x){
    int b = blockIdx.y;
    const float4* xb = (const float4*)(x + (size_t)b*PLANE);
    float mn = 3.4e38f, mx = -3.4e38f;
    for (int i = blockIdx.x*blockDim.x + threadIdx.x; i < PLANE/4; i += gridDim.x*blockDim.x){
        float4 v = xb[i];
        mn = fminf(mn, fminf(fminf(v.x, v.y), fminf(v.z, v.w)));
        mx = fmaxf(mx, fmaxf(fmaxf(v.x, v.y), fmaxf(v.z, v.w)));
    }
    #pragma unroll
    for (int o = 16; o; o >>= 1){
        mn = fminf(mn, __shfl_down_sync(~0u, mn, o));
        mx = fmaxf(mx, __shfl_down_sync(~0u, mx, o));
    }
    __shared__ float smn[8], smx[8];
    int w = threadIdx.x >> 5, l = threadIdx.x & 31;
    if (l == 0){ smn[w] = mn; smx[w] = mx; }
    __syncthreads();
    if (threadIdx.x < 8){
        mn = smn[threadIdx.x]; mx = smx[threadIdx.x];
        #pragma unroll
        for (int o = 4; o; o >>= 1){
            mn = fminf(mn, __shfl_down_sync(0xff, mn, o));
            mx = fmaxf(mx, __shfl_down_sync(0xff, mx, o));
        }
        if (threadIdx.x == 0){
            atomicMin(&g_umin[b], fmap(mn));
            atomicMax(&g_umax[b], fmap(mx));
        }
    }
}

// -------- K2a: normalize + row prefix (writes padded SAT rows; row 0 = zeros) --------
__global__ void k2a_rowpref(const float* __restrict__ x){
    int b = blockIdx.y, hh = blockIdx.x, c = threadIdx.x;
    float* satb = g_sat + (size_t)b*SATPLANE;
    if (hh == 0){
        for (int w = 0; w < SATW; w++) satb[w*NC + c] = 0.f;
        return;
    }
    int h = hh - 1;
    float xmin = funmap(g_umin[b]);
    float xmax = funmap(g_umax[b]);
    float inv  = 1.f/(xmax - xmin + EPS);
    const float* xr = x + ((size_t)(b*NH + h))*NW*NC + c;
    float* sr = satb + (size_t)hh*SATROW + c;
    sr[0] = 0.f;
    float acc = 0.f;
    for (int w = 0; w < NW; w++){
        float xs = (xr[w*NC] - xmin)*inv;
        acc += xs - 0.5f;                // store centered values for precision
        sr[(w+1)*NC] = acc;
    }
}

// -------- K2b: column prefix, 4-way chunked (14 rows/thread) --------
__global__ void k2b_colpref(){
    int b = blockIdx.y;
    int t = threadIdx.x;                    // 0..255
    int p = t & 63;                         // pair within block
    int chunk = t >> 6;                     // 0..3
    int pairIdx = blockIdx.x*64 + p;        // 0..7167 : (cw, c)
    int cw = pairIdx >> 7, c = pairIdx & 127;
    float* base = g_sat + (size_t)b*SATPLANE + (size_t)(cw+1)*NC + c;
    int h0 = chunk*14 + 1;                  // rows hh = h0..h0+13
    float v[14]; float acc = 0.f;
    #pragma unroll
    for (int i = 0; i < 14; i++){
        acc += base[(size_t)(h0+i)*SATROW];
        v[i] = acc;
    }
    __shared__ float tot[4][64];
    tot[chunk][p] = acc;
    __syncthreads();
    float off = 0.f;
    #pragma unroll
    for (int j = 0; j < 3; j++) if (j < chunk) off += tot[j][p];
    #pragma unroll
    for (int i = 0; i < 14; i++)
        base[(size_t)(h0+i)*SATROW] = v[i] + off;
}

// -------- K3: main per-pixel kernel --------
__global__ void __launch_bounds__(256) k3_main(
    const float* __restrict__ x,
    const float* __restrict__ gamma, const float* __restrict__ beta,
    const float* __restrict__ bnm,   const float* __restrict__ bnv)
{
    int b = blockIdx.y, h = blockIdx.x;
    int c = threadIdx.x & 127, half = threadIdx.x >> 7;
    const float* __restrict__ satb = g_sat + (size_t)b*SATPLANE + c;

    float xmin = funmap(g_umin[b]);
    float inv  = 1.f/(funmap(g_umax[b]) - xmin + EPS);
    float u0 = g_u[0], u1 = g_u[1], u2 = g_u[2], u3 = g_u[3], u4 = g_u[4];
    float normu = g_normu;
    float ga = gamma[c], be = beta[c], bm = bnm[c];
    float rstd = rsqrtf(bnv[c] + 1e-3f);

    // 32-bit element offsets (from satb) instead of 64-bit pointers
    int offA[5], offB[5], lo[5], hi[5];
    float rhf[5];
    #pragma unroll
    for (int s = 0; s < 5; s++){
        int k = 2 << s;                  // 2,4,8,16,32
        lo[s] = k/2 - 1; hi[s] = k/2;    // TF SAME padding for even k
        int r0 = max(0, h - lo[s]), r1 = min(NH-1, h + hi[s]);
        offA[s] = r0    *SATROW;         // = S(r0-1, .)
        offB[s] = (r1+1)*SATROW;         // = S(r1,   .)
        rhf[s]  = (float)(r1 - r0 + 1);
    }

    float asum = 0.f;
    int wbeg = half*28;
    #pragma unroll 4
    for (int w = wbeg; w < wbeg + 28; w++){
        float lm[5], slm = 0.f;
        #pragma unroll
        for (int s = 0; s < 5; s++){
            int cA = max(0, w - lo[s]) << 7;          // padded-SAT col * NC
            int cB = (min(NW-1, w + hi[s]) + 1) << 7;
            float Ssum = satb[offB[s] + cB] - satb[offA[s] + cB]
                       - satb[offB[s] + cA] + satb[offA[s] + cA];
            float m = Ssum + 0.5f*rhf[s]*(float)((cB - cA) >> 7);  // undo centering
            lm[s] = __logf(m + EPS);
            slm += lm[s];
        }
        float alpha = (-2.f*lm[0] - lm[1] + lm[3] + 2.f*lm[4]) * (1.f/(10.f*LN2));
        float mean = 0.2f*slm;
        float a0 = lm[0]-mean, a1 = lm[1]-mean, a2 = lm[2]-mean, a3 = lm[3]-mean, a4 = lm[4]-mean;
        float dot = a0*u0 + a1*u1 + a2*u2 + a3*u3 + a4*u4;
        float na  = sqrtf(a0*a0 + a1*a1 + a2*a2 + a3*a3 + a4*a4);
        float cosv = alpha*dot / (na*fabsf(alpha)*normu + EPS);
        float sim = 0.5f*(cosv + 1.f);
        float an = ga*(alpha - bm)*rstd + be;
        float sa = 1.f/(1.f + __expf(-an));
        size_t o = ((size_t)(b*NH + h)*NW + w)*NC + c;
        float xs = (x[o] - xmin)*inv;
        // pack P = sim*sa, Q = (1-sim)*xs (both in [0,1]) as unorm16 pair
        unsigned pv = __float2uint_rn(__saturatef(sim*sa)*65535.f);
        unsigned qv = __float2uint_rn(__saturatef((1.f - sim)*xs)*65535.f);
        g_PQ[o] = pv | (qv << 16);
        asum += alpha;
    }
    __shared__ float sh[256];
    sh[threadIdx.x] = asum;
    __syncthreads();
    if (half == 0)
        g_part[((size_t)b*NH + h)*NC + c] = sh[c] + sh[c + 128];
}

// -------- K4: squeeze-excite MLP --------
__global__ void k4_se(const float* __restrict__ W1, const float* __restrict__ b1,
                      const float* __restrict__ W2, const float* __restrict__ b2){
    int b = blockIdx.x, t = threadIdx.x;
    __shared__ float sq[NC], hid[16];
    float s = 0.f;
    const float* pb = g_part + (size_t)b*NH*NC + t;
    for (int h = 0; h < NH; h++) s += pb[h*NC];
    sq[t] = s * (1.f/(float)HW);
    __syncthreads();
    if (t < 16){
        float a = b1[t];
        #pragma unroll 8
        for (int cc = 0; cc < NC; cc++) a += sq[cc]*W1[cc*16 + t];
        hid[t] = fmaxf(a, 0.f);
    }
    __syncthreads();
    float e = b2[t];
    #pragma unroll
    for (int j = 0; j < 16; j++) e += hid[j]*W2[j*NC + t];
    g_excite[b*NC + t] = 1.f/(1.f + expf(-e));
}

// -------- K5: final combine (packed read) --------
__global__ void k5_out(float* __restrict__ out){
    const float inv16 = 1.f/65535.f;
    for (int i4 = blockIdx.x*blockDim.x + threadIdx.x; i4 < NTOT/4;
         i4 += gridDim.x*blockDim.x){
        size_t i = (size_t)i4*4;
        int b  = (int)(i / PLANE);
        int c0 = (int)(i & 127);
        uint4 pq = *(const uint4*)(g_PQ + i);
        float4 E = *(const float4*)(g_excite + b*NC + c0);
        float4 o;
        o.x = (float)(pq.x & 0xFFFFu)*inv16 + (float)(pq.x >> 16)*inv16*E.x;
        o.y = (float)(pq.y & 0xFFFFu)*inv16 + (float)(pq.y >> 16)*inv16*E.y;
        o.z = (float)(pq.z & 0xFFFFu)*inv16 + (float)(pq.z >> 16)*inv16*E.z;
        o.w = (float)(pq.w & 0xFFFFu)*inv16 + (float)(pq.w >> 16)*inv16*E.w;
        *(float4*)(out + i) = o;
    }
}

extern "C" void kernel_launch(void* const* d_in, const int* in_sizes, int n_in,
                              void* d_out, int out_size){
    const float* x     = (const float*)d_in[0];
    const float* kappa = (const float*)d_in[1];
    const float* W1    = (const float*)d_in[2];
    const float* b1    = (const float*)d_in[3];
    const float* W2    = (const float*)d_in[4];
    const float* b2    = (const float*)d_in[5];
    const float* gamma = (const float*)d_in[6];
    const float* beta  = (const float*)d_in[7];
    const float* bnm   = (const float*)d_in[8];
    const float* bnv   = (const float*)d_in[9];
    float* out = (float*)d_out;

    k0_init   <<<1, 256>>>(kappa);
    k1_minmax <<<dim3(32, NB), 256>>>(x);
    k2a_rowpref<<<dim3(SATW, NB), 128>>>(x);
    k2b_colpref<<<dim3(112, NB), 256>>>();
    k3_main   <<<dim3(NH, NB), 256>>>(x, gamma, beta, bnm, bnv);
    k4_se     <<<NB, 128>>>(W1, b1, W2, b2);
    k5_out    <<<(NTOT/4 + 255)/256, 256>>>(out);
}

// round 14
// speedup vs baseline: 1.3180x; 1.1109x over previous
#include <cuda_runtime.h>

#define EPS 1e-7f
#define LN2 0.69314718055994530942f

#define NB 16
#define NH 56
#define NW 56
#define NC 128
#define HW   (NH*NW)                 // 3136
#define PLANE (NH*NW*NC)             // 401408
#define NTOT (NB*NH*NW*NC)           // 6422528
#define SATW 57
#define SATROW (SATW*NC)             // 7296
#define SATPLANE (SATW*SATW*NC)      // 415872

// -------- scratch (static device globals; no runtime allocation) --------
__device__ float    g_sat[(size_t)NB*SATPLANE];   // padded SAT of (xs-0.5)
__device__ unsigned g_PQ[NTOT];                   // packed unorm16: P | Q<<16
// statically initialized for the FIRST execution; k5 re-inits for replays
__device__ unsigned g_umin[NB] = {
    0xFFFFFFFFu,0xFFFFFFFFu,0xFFFFFFFFu,0xFFFFFFFFu,
    0xFFFFFFFFu,0xFFFFFFFFu,0xFFFFFFFFu,0xFFFFFFFFu,
    0xFFFFFFFFu,0xFFFFFFFFu,0xFFFFFFFFu,0xFFFFFFFFu,
    0xFFFFFFFFu,0xFFFFFFFFu,0xFFFFFFFFu,0xFFFFFFFFu};
__device__ unsigned g_umax[NB];                   // zero-initialized
__device__ float    g_part[NB*NH*NC];             // per-(b,h,c) alpha partial sums
__device__ float    g_excite[NB*NC];
__device__ float    g_u[5];
__device__ float    g_normu;

// order-preserving float <-> uint mapping for atomic min/max
__device__ __forceinline__ unsigned fmap(float f){
    unsigned u = __float_as_uint(f);
    return (u >> 31) ? ~u : (u | 0x80000000u);
}
__device__ __forceinline__ float funmap(unsigned u){
    return __uint_as_float((u >> 31) ? (u & 0x7fffffffu) : ~u);
}

// -------- K1: per-sample min/max (float4) + kappa precompute (one thread) --------
__global__ void k1_minmax(const float* __restrict__ x, const float* __restrict__ kappa){
    int b = blockIdx.y;
    if (blockIdx.x == 0 && b == 0 && threadIdx.x == 0){
        float v[5], mean = 0.f;
        #pragma unroll
        for (int s = 0; s < 5; s++){
            float kk = 1.f/(1.f + expf(-kappa[s]));          // sigmoid(kappa)
            float lk = 1.f/(1.f + expf(-logf(kk + EPS)));    // sigmoid(log(k_+eps))
            v[s] = lk + (float)(s+1)*LN2;                    // log_k + log_r
            mean += v[s];
        }
        mean *= 0.2f;
        float n2 = 0.f;
        #pragma unroll
        for (int s = 0; s < 5; s++){ g_u[s] = v[s] - mean; n2 += g_u[s]*g_u[s]; }
        g_normu = sqrtf(n2);
    }
    const float4* xb = (const float4*)(x + (size_t)b*PLANE);
    float mn = 3.4e38f, mx = -3.4e38f;
    for (int i = blockIdx.x*blockDim.x + threadIdx.x; i < PLANE/4; i += gridDim.x*blockDim.x){
        float4 v = xb[i];
        mn = fminf(mn, fminf(fminf(v.x, v.y), fminf(v.z, v.w)));
        mx = fmaxf(mx, fmaxf(fmaxf(v.x, v.y), fmaxf(v.z, v.w)));
    }
    #pragma unroll
    for (int o = 16; o; o >>= 1){
        mn = fminf(mn, __shfl_down_sync(~0u, mn, o));
        mx = fmaxf(mx, __shfl_down_sync(~0u, mx, o));
    }
    __shared__ float smn[8], smx[8];
    int w = threadIdx.x >> 5, l = threadIdx.x & 31;
    if (l == 0){ smn[w] = mn; smx[w] = mx; }
    __syncthreads();
    if (threadIdx.x < 8){
        mn = smn[threadIdx.x]; mx = smx[threadIdx.x];
        #pragma unroll
        for (int o = 4; o; o >>= 1){
            mn = fminf(mn, __shfl_down_sync(0xff, mn, o));
            mx = fmaxf(mx, __shfl_down_sync(0xff, mx, o));
        }
        if (threadIdx.x == 0){
            atomicMin(&g_umin[b], fmap(mn));
            atomicMax(&g_umax[b], fmap(mx));
        }
    }
}

// -------- K2a: normalize + row prefix (writes padded SAT rows; row 0 = zeros) --------
__global__ void k2a_rowpref(const float* __restrict__ x){
    int b = blockIdx.y, hh = blockIdx.x, c = threadIdx.x;
    float* satb = g_sat + (size_t)b*SATPLANE;
    if (hh == 0){
        for (int w = 0; w < SATW; w++) satb[w*NC + c] = 0.f;
        return;
    }
    int h = hh - 1;
    float xmin = funmap(g_umin[b]);
    float xmax = funmap(g_umax[b]);
    float inv  = 1.f/(xmax - xmin + EPS);
    const float* xr = x + ((size_t)(b*NH + h))*NW*NC + c;
    float* sr = satb + (size_t)hh*SATROW + c;
    sr[0] = 0.f;
    float acc = 0.f;
    for (int w = 0; w < NW; w++){
        float xs = (xr[w*NC] - xmin)*inv;
        acc += xs - 0.5f;                // store centered values for precision
        sr[(w+1)*NC] = acc;
    }
}

// -------- K2b: column prefix, 4-way chunked (14 rows/thread) --------
__global__ void k2b_colpref(){
    int b = blockIdx.y;
    int t = threadIdx.x;                    // 0..255
    int p = t & 63;                         // pair within block
    int chunk = t >> 6;                     // 0..3
    int pairIdx = blockIdx.x*64 + p;        // 0..7167 : (cw, c)
    int cw = pairIdx >> 7, c = pairIdx & 127;
    float* base = g_sat + (size_t)b*SATPLANE + (size_t)(cw+1)*NC + c;
    int h0 = chunk*14 + 1;                  // rows hh = h0..h0+13
    float v[14]; float acc = 0.f;
    #pragma unroll
    for (int i = 0; i < 14; i++){
        acc += base[(size_t)(h0+i)*SATROW];
        v[i] = acc;
    }
    __shared__ float tot[4][64];
    tot[chunk][p] = acc;
    __syncthreads();
    float off = 0.f;
    #pragma unroll
    for (int j = 0; j < 3; j++) if (j < chunk) off += tot[j][p];
    #pragma unroll
    for (int i = 0; i < 14; i++)
        base[(size_t)(h0+i)*SATROW] = v[i] + off;
}

// -------- K3: main per-pixel kernel --------
__global__ void __launch_bounds__(256) k3_main(
    const float* __restrict__ x,
    const float* __restrict__ gamma, const float* __restrict__ beta,
    const float* __restrict__ bnm,   const float* __restrict__ bnv)
{
    int b = blockIdx.y, h = blockIdx.x;
    int c = threadIdx.x & 127, half = threadIdx.x >> 7;
    const float* __restrict__ satb = g_sat + (size_t)b*SATPLANE + c;

    float xmin = funmap(g_umin[b]);
    float inv  = 1.f/(funmap(g_umax[b]) - xmin + EPS);
    float u0 = g_u[0], u1 = g_u[1], u2 = g_u[2], u3 = g_u[3], u4 = g_u[4];
    float normu = g_normu;
    float ga = gamma[c], be = beta[c], bm = bnm[c];
    float rstd = rsqrtf(bnv[c] + 1e-3f);

    // 32-bit element offsets (from satb) instead of 64-bit pointers
    int offA[5], offB[5], lo[5], hi[5];
    float rhf[5];
    #pragma unroll
    for (int s = 0; s < 5; s++){
        int k = 2 << s;                  // 2,4,8,16,32
        lo[s] = k/2 - 1; hi[s] = k/2;    // TF SAME padding for even k
        int r0 = max(0, h - lo[s]), r1 = min(NH-1, h + hi[s]);
        offA[s] = r0    *SATROW;         // = S(r0-1, .)
        offB[s] = (r1+1)*SATROW;         // = S(r1,   .)
        rhf[s]  = (float)(r1 - r0 + 1);
    }

    float asum = 0.f;
    int wbeg = half*28;
    #pragma unroll 4
    for (int w = wbeg; w < wbeg + 28; w++){
        float lm[5], slm = 0.f;
        #pragma unroll
        for (int s = 0; s < 5; s++){
            int cA = max(0, w - lo[s]) << 7;          // padded-SAT col * NC
            int cB = (min(NW-1, w + hi[s]) + 1) << 7;
            float Ssum = satb[offB[s] + cB] - satb[offA[s] + cB]
                       - satb[offB[s] + cA] + satb[offA[s] + cA];
            float m = Ssum + 0.5f*rhf[s]*(float)((cB - cA) >> 7);  // undo centering
            lm[s] = __logf(m + EPS);
            slm += lm[s];
        }
        float alpha = (-2.f*lm[0] - lm[1] + lm[3] + 2.f*lm[4]) * (1.f/(10.f*LN2));
        float mean = 0.2f*slm;
        float a0 = lm[0]-mean, a1 = lm[1]-mean, a2 = lm[2]-mean, a3 = lm[3]-mean, a4 = lm[4]-mean;
        float dot = a0*u0 + a1*u1 + a2*u2 + a3*u3 + a4*u4;
        float na  = sqrtf(a0*a0 + a1*a1 + a2*a2 + a3*a3 + a4*a4);
        float cosv = __fdividef(alpha*dot, na*fabsf(alpha)*normu + EPS);
        float sim = 0.5f*(cosv + 1.f);
        float an = ga*(alpha - bm)*rstd + be;
        float sa = __fdividef(1.f, 1.f + __expf(-an));
        size_t o = ((size_t)(b*NH + h)*NW + w)*NC + c;
        float xs = (x[o] - xmin)*inv;
        // pack P = sim*sa, Q = (1-sim)*xs (both in [0,1]) as unorm16 pair
        unsigned pv = __float2uint_rn(__saturatef(sim*sa)*65535.f);
        unsigned qv = __float2uint_rn(__saturatef((1.f - sim)*xs)*65535.f);
        g_PQ[o] = pv | (qv << 16);
        asum += alpha;
    }
    __shared__ float sh[256];
    sh[threadIdx.x] = asum;
    __syncthreads();
    if (half == 0)
        g_part[((size_t)b*NH + h)*NC + c] = sh[c] + sh[c + 128];
}

// -------- K4: squeeze-excite MLP --------
__global__ void k4_se(const float* __restrict__ W1, const float* __restrict__ b1,
                      const float* __restrict__ W2, const float* __restrict__ b2){
    int b = blockIdx.x, t = threadIdx.x;
    __shared__ float sq[NC], hid[16];
    float s = 0.f;
    const float* pb = g_part + (size_t)b*NH*NC + t;
    for (int h = 0; h < NH; h++) s += pb[h*NC];
    sq[t] = s * (1.f/(float)HW);
    __syncthreads();
    if (t < 16){
        float a = b1[t];
        #pragma unroll 8
        for (int cc = 0; cc < NC; cc++) a += sq[cc]*W1[cc*16 + t];
        hid[t] = fmaxf(a, 0.f);
    }
    __syncthreads();
    float e = b2[t];
    #pragma unroll
    for (int j = 0; j < 16; j++) e += hid[j]*W2[j*NC + t];
    g_excite[b*NC + t] = 1.f/(1.f + expf(-e));
}

// -------- K5: final combine (packed read) + min/max re-init for next replay --------
__global__ void k5_out(float* __restrict__ out){
    if (blockIdx.x == 0 && threadIdx.x < NB){
        g_umin[threadIdx.x] = 0xFFFFFFFFu;
        g_umax[threadIdx.x] = 0u;
    }
    const float inv16 = 1.f/65535.f;
    for (int i4 = blockIdx.x*blockDim.x + threadIdx.x; i4 < NTOT/4;
         i4 += gridDim.x*blockDim.x){
        size_t i = (size_t)i4*4;
        int b  = (int)(i / PLANE);
        int c0 = (int)(i & 127);
        uint4 pq = *(const uint4*)(g_PQ + i);
        float4 E = *(const float4*)(g_excite + b*NC + c0);
        float4 o;
        o.x = (float)(pq.x & 0xFFFFu)*inv16 + (float)(pq.x >> 16)*inv16*E.x;
        o.y = (float)(pq.y & 0xFFFFu)*inv16 + (float)(pq.y >> 16)*inv16*E.y;
        o.z = (float)(pq.z & 0xFFFFu)*inv16 + (float)(pq.z >> 16)*inv16*E.z;
        o.w = (float)(pq.w & 0xFFFFu)*inv16 + (float)(pq.w >> 16)*inv16*E.w;
        *(float4*)(out + i) = o;
    }
}

extern "C" void kernel_launch(void* const* d_in, const int* in_sizes, int n_in,
                              void* d_out, int out_size){
    const float* x     = (const float*)d_in[0];
    const float* kappa = (const float*)d_in[1];
    const float* W1    = (const float*)d_in[2];
    const float* b1    = (const float*)d_in[3];
    const float* W2    = (const float*)d_in[4];
    const float* b2    = (const float*)d_in[5];
    const float* gamma = (const float*)d_in[6];
    const float* beta  = (const float*)d_in[7];
    const float* bnm   = (const float*)d_in[8];
    const float* bnv   = (const float*)d_in[9];
    float* out = (float*)d_out;

    k1_minmax <<<dim3(32, NB), 256>>>(x, kappa);
    k2a_rowpref<<<dim3(SATW, NB), 128>>>(x);
    k2b_colpref<<<dim3(112, NB), 256>>>();
    k3_main   <<<dim3(NH, NB), 256>>>(x, gamma, beta, bnm, bnv);
    k4_se     <<<NB, 128>>>(W1, b1, W2, b2);
    k5_out    <<<(NTOT/4 + 255)/256, 256>>>(out);
}